// round 15
// baseline (speedup 1.0000x reference)
#include <cuda_runtime.h>

#define BB 16
#define HH 512
#define WW 512
#define HW (HH*WW)
#define NN (BB*HW)
#define WPR 16                 // words per row
#define WPI (HH*WPR)           // words per image = 8192
#define TOT (BB*WPI)           // total words = 131072

// bit j of word (b,y,w) = pixel x = w*32 + j ; pixel index = 32*wordIdx + j

__device__ unsigned g_F[TOT];
__device__ unsigned g_G[TOT];
__device__ int g_L[NN];
__device__ int g_sz[NN];
__device__ int g_nc[BB];

// ---------------- pack: float4/thread, word assembly via shfl ----------------
__global__ void k_pack(const float* __restrict__ in) {
    int g = blockIdx.x * blockDim.x + threadIdx.x;   // one thread = 4 pixels
    float4 f = ((const float4*)in)[g];
    unsigned n = (f.x > 0.0f ? 1u : 0u) | (f.y > 0.0f ? 2u : 0u)
               | (f.z > 0.0f ? 4u : 0u) | (f.w > 0.0f ? 8u : 0u);
    unsigned v = n  | (__shfl_xor_sync(0xffffffffu, n, 1) << 4);
    v = (v & 0xffu)   | ((__shfl_xor_sync(0xffffffffu, v, 2) & 0xffu)   << 8);
    v = (v & 0xffffu) | ((__shfl_xor_sync(0xffffffffu, v, 4) & 0xffffu) << 16);
    int lane = g & 31;
    if ((lane & 7) == 0) g_F[((g >> 5) << 2) + (lane >> 3)] = v;
}

// ---------------- bit helpers ----------------
__device__ __forceinline__ int runlen(unsigned m, int j) {
    unsigned nt = ~(m >> j);
    return nt ? (__ffs(nt) - 1) : (32 - j);
}
__device__ __forceinline__ unsigned runmask(int j, int e) {
    return (e >= 32) ? 0xffffffffu : (((1u << e) - 1u) << j);
}
// start bit of the in-word run of m containing set bit j
__device__ __forceinline__ int rstart(unsigned m, int j) {
    unsigned zeros = (~m) & (j ? ((1u << j) - 1u) : 0u);
    return zeros ? (32 - __clz(zeros)) : 0;
}

// ---------------- union-find ----------------
// Root chase with atomicCAS path-halving. Safe vs concurrent atomicMin:
// CAS fails if the slot changed; all writers only decrease toward ancestors.
__device__ __forceinline__ int findroot_h(int i) {
    volatile int* V = g_L;
    int p;
    while ((p = V[i]) != i) {
        int gp = V[p];
        if (gp == p) return p;
        atomicCAS(&g_L[i], p, gp);
        i = gp;
    }
    return i;
}

__device__ void unite(int a, int b) {
    while (true) {
        a = findroot_h(a);
        b = findroot_h(b);
        if (a == b) return;
        if (a > b) { int t = a; a = b; b = t; }
        int old = atomicMin(&g_L[b], a);
        if (old == b) return;
        b = old;
    }
}

// resolve root at a run start (immediate when count-compression held)
__device__ __forceinline__ int root_at(int i) {
    int r = g_L[i];
    while (g_L[r] != r) r = g_L[r];
    return r;
}

// ---------------- CCL kernels: ONE WARP PER WORD (INV: label the zero bits) ----
// init: lane j writes label/size iff a run starts at bit j
template<bool INV>
__global__ void k_cinit(const unsigned* __restrict__ F) {
    int g = blockIdx.x * blockDim.x + threadIdx.x;
    int t = g >> 5, lane = g & 31;
    if (g < BB) g_nc[g] = 0;
    unsigned m = F[t]; if (INV) m = ~m;
    unsigned starts = m & ~(m << 1);
    if ((starts >> lane) & 1u) {
        g_L[t * 32 + lane]  = t * 32 + lane;
        g_sz[t * 32 + lane] = 0;
    }
}

template<bool INV>
__global__ void k_merge(const unsigned* __restrict__ F) {
    int g = blockIdx.x * blockDim.x + threadIdx.x;
    int t = g >> 5, lane = g & 31;
    int w = t & 15, y = (t >> 4) & 511;
    unsigned cur = F[t]; if (INV) cur = ~cur;
    if (!cur) return;
    int base = t * 32;
    // horizontal stitch across word boundary (lane 0)
    if (lane == 0 && w > 0 && (cur & 1u)) {
        unsigned left = F[t - 1]; if (INV) left = ~left;
        if (left >> 31) unite(base, (t - 1) * 32 + rstart(left, 31));
    }
    // vertical: lane j handles the overlap-segment start at bit j (parallel chases)
    if (y > 0) {
        unsigned up = F[t - WPR]; if (INV) up = ~up;
        unsigned ov = cur & up;
        unsigned vst = ov & ~(ov << 1);
        if ((vst >> lane) & 1u)
            unite(base + rstart(cur, lane), base - WW + rstart(up, lane));
    }
}

// count sizes: lane j owns run starting at bit j; warp-aggregated atomics
template<bool INV, bool NC>
__global__ void k_count(const unsigned* __restrict__ F) {
    int g = blockIdx.x * blockDim.x + threadIdx.x;
    int t = g >> 5, lane = g & 31;
    unsigned m = F[t]; if (INV) m = ~m;
    if (!m) return;
    int base = t * 32, b = t >> 13;
    unsigned starts = m & ~(m << 1);
    bool is = (starts >> lane) & 1u;
    unsigned act = __ballot_sync(0xffffffffu, is);
    if (!is) return;
    int e = runlen(m, lane);
    int i = base + lane;
    int r = findroot_h(i);                 // all run lanes chase concurrently
    g_L[i] = r;                            // owner-only write of final root
    unsigned grp = __match_any_sync(act, r);
    int tot = __reduce_add_sync(grp, e);
    if ((int)(__ffs(grp) - 1) == lane) atomicAdd(&g_sz[r], tot);
    if (NC && r == i) atomicAdd(&g_nc[b], 1);
}

__global__ void k_filter(unsigned* F, int min_size) {
    int g = blockIdx.x * blockDim.x + threadIdx.x;
    int t = g >> 5, lane = g & 31;
    unsigned m = F[t];
    if (!m) return;
    if (g_nc[t >> 13] <= 1) return;
    unsigned starts = m & ~(m << 1);
    unsigned del = 0;
    if ((starts >> lane) & 1u) {
        int e = runlen(m, lane);
        if (g_sz[root_at(t * 32 + lane)] < min_size) del = runmask(lane, e);
    }
    del = __reduce_or_sync(0xffffffffu, del);
    if (lane == 0 && del) F[t] = m & ~del;
}

__global__ void k_fill(unsigned* F, int thresh) {
    int g = blockIdx.x * blockDim.x + threadIdx.x;
    int t = g >> 5, lane = g & 31;
    unsigned m = ~F[t];                    // background bits
    if (!m) return;
    unsigned starts = m & ~(m << 1);
    unsigned add = 0;
    if ((starts >> lane) & 1u) {
        int e = runlen(m, lane);
        if (g_sz[root_at(t * 32 + lane)] < thresh) add = runmask(lane, e);
    }
    add = __reduce_or_sync(0xffffffffu, add);
    if (lane == 0 && add) F[t] |= add;
}

// ---------------- morphology on bitpacked (thread per word) ----------------
__host__ __device__ constexpr int hwidth(int R, int dy) {
    int w = 0;
    while ((w + 1) * (w + 1) + dy * dy <= R * R) ++w;
    return w;
}

template<int R, bool ER>
__global__ void k_morph(const unsigned* __restrict__ in, unsigned* __restrict__ out) {
    int t = blockIdx.x * blockDim.x + threadIdx.x;
    int w = t & 15, y = (t >> 4) & 511, b = t >> 13;
    const unsigned* img = in + b * WPI;
    const unsigned border = ER ? 0xffffffffu : 0u;
    unsigned acc = border;
#pragma unroll
    for (int dy = -R; dy <= R; dy++) {
        int yy = y + dy;
        unsigned c, l, r;
        if (yy < 0 || yy >= HH) { c = border; l = border; r = border; }
        else {
            c = img[yy * WPR + w];
            l = (w > 0)  ? img[yy * WPR + w - 1] : border;
            r = (w < 15) ? img[yy * WPR + w + 1] : border;
        }
        unsigned rowacc = c;
        const int wd = hwidth(R, dy);
#pragma unroll
        for (int s = 1; s <= wd; s++) {
            unsigned rs = __funnelshift_r(c, r, s);   // sample x+s
            unsigned ls = __funnelshift_l(l, c, s);   // sample x-s
            if (ER) rowacc &= rs & ls; else rowacc |= rs | ls;
        }
        if (ER) acc &= rowacc; else acc |= rowacc;
    }
    out[t] = acc;
}

// ---------------- final dilate(disk1) + unpack float ----------------
__global__ void k_out(const unsigned* __restrict__ in, float* __restrict__ out) {
    int g = blockIdx.x * blockDim.x + threadIdx.x;
    int lane = g & 31;
    int t = g >> 5;
    int w = t & 15, y = (t >> 4) & 511, b = t >> 13;
    const unsigned* img = in + b * WPI;
    unsigned c = img[y * WPR + w];
    unsigned l = (w > 0)   ? img[y * WPR + w - 1] : 0u;
    unsigned r = (w < 15)  ? img[y * WPR + w + 1] : 0u;
    unsigned u = (y > 0)   ? img[(y - 1) * WPR + w] : 0u;
    unsigned d = (y < 511) ? img[(y + 1) * WPR + w] : 0u;
    unsigned res = c | u | d | __funnelshift_r(c, r, 1) | __funnelshift_l(l, c, 1);
    out[b * HW + y * WW + w * 32 + lane] = (float)((res >> lane) & 1u);
}

// ---------------- launch ----------------
extern "C" void kernel_launch(void* const* d_in, const int* in_sizes, int n_in,
                              void* d_out, int out_size) {
    (void)in_sizes; (void)n_in; (void)out_size;
    const float* in = (const float*)d_in[0];
    float* out = (float*)d_out;

    unsigned *F, *G;
    cudaGetSymbolAddress((void**)&F, g_F);
    cudaGetSymbolAddress((void**)&G, g_G);

    const int TPB = 256;
    const int gw  = TOT / TPB;         // 512 blocks  (thread-per-word kernels)
    const int gww = TOT / (TPB / 32);  // 16384 blocks (warp-per-word kernels)
    const int gp  = NN / TPB;          // pixel-granular kernels

    // pack: fg = input > 0 (float4 + shfl assembly)
    k_pack<<<NN / 4 / TPB, TPB>>>(in);

    // --- remove_small_objects(fg, 2000, guarded) ---
    k_cinit<false><<<gww, TPB>>>(F);
    k_merge<false><<<gww, TPB>>>(F);
    k_count<false, true><<<gww, TPB>>>(F);
    k_filter<<<gww, TPB>>>(F, 2000);

    // --- fill small holes: bg components < 301 px ---
    k_cinit<true><<<gww, TPB>>>(F);
    k_merge<true><<<gww, TPB>>>(F);
    k_count<true, false><<<gww, TPB>>>(F);
    k_fill<<<gww, TPB>>>(F, 301);

    // --- erode disk(2), then opening disk(5) ---
    k_morph<2, true ><<<gw, TPB>>>(F, G);
    k_morph<5, true ><<<gw, TPB>>>(G, F);
    k_morph<5, false><<<gw, TPB>>>(F, G);

    // --- remove_small_objects(fg, 2000, guarded) on G ---
    k_cinit<false><<<gww, TPB>>>(G);
    k_merge<false><<<gww, TPB>>>(G);
    k_count<false, true><<<gww, TPB>>>(G);
    k_filter<<<gww, TPB>>>(G, 2000);

    // --- dilate disk(1) -> float out ---
    k_out<<<gp, TPB>>>(G, out);
}

// round 16
// speedup vs baseline: 2.3880x; 2.3880x over previous
#include <cuda_runtime.h>

#define BB 16
#define HH 512
#define WW 512
#define HW (HH*WW)
#define NN (BB*HW)
#define WPR 16                 // words per row
#define WPI (HH*WPR)           // words per image = 8192
#define TOT (BB*WPI)           // total words = 131072

// bit j of word (b,y,w) = pixel x = w*32 + j ; pixel index = 32*wordIdx + j

__device__ unsigned g_F[TOT];
__device__ unsigned g_G[TOT];
// double-buffered union-find: CCL1 & CCL3 -> buf 0, hole-CCL -> buf 1
__device__ int g_L0[NN];
__device__ int g_S0[NN];
__device__ int g_L1[NN];
__device__ int g_S1[NN];
__device__ int g_nc[BB];

// ---------------- bit helpers ----------------
__device__ __forceinline__ int runlen(unsigned m, int j) {
    unsigned nt = ~(m >> j);
    return nt ? (__ffs(nt) - 1) : (32 - j);
}
__device__ __forceinline__ unsigned runmask(int j, int e) {
    return (e >= 32) ? 0xffffffffu : (((1u << e) - 1u) << j);
}
// start bit of the in-word run of m containing set bit j
__device__ __forceinline__ int rstart(unsigned m, int j) {
    unsigned zeros = (~m) & (j ? ((1u << j) - 1u) : 0u);
    return zeros ? (32 - __clz(zeros)) : 0;
}
// init labels+sizes at in-word run starts of mask m in word t
__device__ __forceinline__ void init_runs(unsigned m, int t, int* L, int* S) {
    int base = t * 32;
    while (m) {
        int j = __ffs(m) - 1;
        int e = runlen(m, j);
        L[base + j] = base + j;
        S[base + j] = 0;
        m &= ~runmask(j, e);
    }
}

// ---------------- union-find ----------------
// Root chase with atomicCAS path-halving. Safe vs concurrent atomicMin:
// CAS fails if the slot changed; all writers only decrease toward ancestors.
__device__ __forceinline__ int findroot_h(int* L, int i) {
    volatile int* V = L;
    int p;
    while ((p = V[i]) != i) {
        int gp = V[p];
        if (gp == p) return p;
        atomicCAS(&L[i], p, gp);
        i = gp;
    }
    return i;
}

__device__ void unite(int* L, int a, int b) {
    while (true) {
        a = findroot_h(L, a);
        b = findroot_h(L, b);
        if (a == b) return;
        if (a > b) { int t = a; a = b; b = t; }
        int old = atomicMin(&L[b], a);
        if (old == b) return;
        b = old;
    }
}

// resolve root at a run start (immediate when count-compression held)
__device__ __forceinline__ int root_at(const int* L, int i) {
    int r = L[i];
    while (L[r] != r) r = L[r];
    return r;
}

// ---------------- pack: float4/thread + shfl word assembly; + init CCL1 ----------------
__global__ void k_pack(const float* __restrict__ in) {
    int g = blockIdx.x * blockDim.x + threadIdx.x;   // one thread = 4 pixels
    float4 f = ((const float4*)in)[g];
    unsigned n = (f.x > 0.0f ? 1u : 0u) | (f.y > 0.0f ? 2u : 0u)
               | (f.z > 0.0f ? 4u : 0u) | (f.w > 0.0f ? 8u : 0u);
    unsigned v = n  | (__shfl_xor_sync(0xffffffffu, n, 1) << 4);
    v = (v & 0xffu)   | ((__shfl_xor_sync(0xffffffffu, v, 2) & 0xffu)   << 8);
    v = (v & 0xffffu) | ((__shfl_xor_sync(0xffffffffu, v, 4) & 0xffffu) << 16);
    int lane = g & 31;
    if ((lane & 7) == 0) {
        int t = ((g >> 5) << 2) + (lane >> 3);
        g_F[t] = v;
        if ((t & (WPI - 1)) == 0) g_nc[t >> 13] = 0;
        init_runs(v, t, g_L0, g_S0);
    }
}

// ---------------- CCL kernels (INV: label the zero bits) ----------------
template<bool INV>
__global__ void k_merge(const unsigned* __restrict__ F, int* L) {
    int t = blockIdx.x * blockDim.x + threadIdx.x;
    int w = t & 15, y = (t >> 4) & 511;
    unsigned cur = F[t]; if (INV) cur = ~cur;
    if (!cur) return;
    int base = t * 32;
    // horizontal stitch across word boundary
    if (w > 0 && (cur & 1u)) {
        unsigned left = F[t - 1]; if (INV) left = ~left;
        if (left >> 31) unite(L, base, (t - 1) * 32 + rstart(left, 31));
    }
    // vertical: one union per overlap-segment start
    if (y > 0) {
        unsigned up = F[t - WPR]; if (INV) up = ~up;
        unsigned ov = cur & up;
        unsigned starts = ov & ~(ov << 1);
        while (starts) {
            int j = __ffs(starts) - 1;
            starts &= starts - 1;
            unite(L, base + rstart(cur, j), base - WW + rstart(up, j));
        }
    }
}

// count sizes; owner-only compression write; warp-aggregated atomics
template<bool INV, bool NC>
__global__ void k_count(const unsigned* __restrict__ F, int* L, int* S) {
    int t = blockIdx.x * blockDim.x + threadIdx.x;
    int lane = threadIdx.x & 31;
    unsigned m = F[t]; if (INV) m = ~m;
    if (!m) return;
    int base = t * 32, b = t >> 13;
    while (m) {
        int j = __ffs(m) - 1;
        int e = runlen(m, j);
        int i = base + j;
        int r = findroot_h(L, i);
        L[i] = r;                        // owner-only write of final root
        unsigned grp = __match_any_sync(__activemask(), (unsigned)r);
        int tot = __reduce_add_sync(grp, e);
        if (lane == __ffs(grp) - 1) atomicAdd(&S[r], tot);
        if (NC && r == i) atomicAdd(&g_nc[b], 1);
        m &= ~runmask(j, e);
    }
}

// filter CCL1 (guarded) + init hole-CCL labels (buf 1) on the inverted result
__global__ void k_filter_init(unsigned* F, int min_size) {
    int t = blockIdx.x * blockDim.x + threadIdx.x;
    unsigned m = F[t];
    unsigned keep = m;
    if (m && g_nc[t >> 13] > 1) {
        int base = t * 32;
        unsigned mm = m;
        while (mm) {
            int j = __ffs(mm) - 1;
            int e = runlen(mm, j);
            if (g_S0[root_at(g_L0, base + j)] < min_size) keep &= ~runmask(j, e);
            mm &= ~runmask(j, e);
        }
        if (keep != m) F[t] = keep;
    }
    init_runs(~keep, t, g_L1, g_S1);     // different buffer -> no race with L0/S0 readers
}

// plain filter (final CCL, buf 0)
__global__ void k_filter(unsigned* F, int min_size) {
    int t = blockIdx.x * blockDim.x + threadIdx.x;
    unsigned m = F[t];
    if (!m) return;
    if (g_nc[t >> 13] <= 1) return;
    int base = t * 32;
    unsigned keep = m, mm = m;
    while (mm) {
        int j = __ffs(mm) - 1;
        int e = runlen(mm, j);
        if (g_S0[root_at(g_L0, base + j)] < min_size) keep &= ~runmask(j, e);
        mm &= ~runmask(j, e);
    }
    if (keep != m) F[t] = keep;
}

__global__ void k_fill(unsigned* F, int thresh) {
    int t = blockIdx.x * blockDim.x + threadIdx.x;
    unsigned m = ~F[t];                  // background bits
    if (!m) return;
    int base = t * 32;
    unsigned add = 0, mm = m;
    while (mm) {
        int j = __ffs(mm) - 1;
        int e = runlen(mm, j);
        if (g_S1[root_at(g_L1, base + j)] < thresh) add |= runmask(j, e);
        mm &= ~runmask(j, e);
    }
    if (add) F[t] |= add;
}

// ---------------- morphology on bitpacked (thread per word) ----------------
__host__ __device__ constexpr int hwidth(int R, int dy) {
    int w = 0;
    while ((w + 1) * (w + 1) + dy * dy <= R * R) ++w;
    return w;
}

template<int R, bool ER, bool INIT>
__global__ void k_morph(const unsigned* __restrict__ in, unsigned* __restrict__ out) {
    int t = blockIdx.x * blockDim.x + threadIdx.x;
    int w = t & 15, y = (t >> 4) & 511, b = t >> 13;
    const unsigned* img = in + b * WPI;
    const unsigned border = ER ? 0xffffffffu : 0u;
    unsigned acc = border;
#pragma unroll
    for (int dy = -R; dy <= R; dy++) {
        int yy = y + dy;
        unsigned c, l, r;
        if (yy < 0 || yy >= HH) { c = border; l = border; r = border; }
        else {
            c = img[yy * WPR + w];
            l = (w > 0)  ? img[yy * WPR + w - 1] : border;
            r = (w < 15) ? img[yy * WPR + w + 1] : border;
        }
        unsigned rowacc = c;
        const int wd = hwidth(R, dy);
#pragma unroll
        for (int s = 1; s <= wd; s++) {
            unsigned rs = __funnelshift_r(c, r, s);   // sample x+s
            unsigned ls = __funnelshift_l(l, c, s);   // sample x-s
            if (ER) rowacc &= rs & ls; else rowacc |= rs | ls;
        }
        if (ER) acc &= rowacc; else acc |= rowacc;
    }
    out[t] = acc;
    if (INIT) {                          // prep CCL3 (buf 0; its readers long finished)
        if ((t & (WPI - 1)) == 0) g_nc[t >> 13] = 0;
        init_runs(acc, t, g_L0, g_S0);
    }
}

// ---------------- final dilate(disk1) + unpack float ----------------
__global__ void k_out(const unsigned* __restrict__ in, float* __restrict__ out) {
    int g = blockIdx.x * blockDim.x + threadIdx.x;
    int lane = g & 31;
    int t = g >> 5;
    int w = t & 15, y = (t >> 4) & 511, b = t >> 13;
    const unsigned* img = in + b * WPI;
    unsigned c = img[y * WPR + w];
    unsigned l = (w > 0)   ? img[y * WPR + w - 1] : 0u;
    unsigned r = (w < 15)  ? img[y * WPR + w + 1] : 0u;
    unsigned u = (y > 0)   ? img[(y - 1) * WPR + w] : 0u;
    unsigned d = (y < 511) ? img[(y + 1) * WPR + w] : 0u;
    unsigned res = c | u | d | __funnelshift_r(c, r, 1) | __funnelshift_l(l, c, 1);
    out[b * HW + y * WW + w * 32 + lane] = (float)((res >> lane) & 1u);
}

// ---------------- launch ----------------
extern "C" void kernel_launch(void* const* d_in, const int* in_sizes, int n_in,
                              void* d_out, int out_size) {
    (void)in_sizes; (void)n_in; (void)out_size;
    const float* in = (const float*)d_in[0];
    float* out = (float*)d_out;

    unsigned *F, *G;
    int *L0, *S0, *L1, *S1;
    cudaGetSymbolAddress((void**)&F,  g_F);
    cudaGetSymbolAddress((void**)&G,  g_G);
    cudaGetSymbolAddress((void**)&L0, g_L0);
    cudaGetSymbolAddress((void**)&S0, g_S0);
    cudaGetSymbolAddress((void**)&L1, g_L1);
    cudaGetSymbolAddress((void**)&S1, g_S1);

    const int TPB = 256;
    const int gw = TOT / TPB;          // 512 blocks, word-granular kernels
    const int gp = NN / TPB;           // pixel-granular kernels

    // pack: fg = input > 0 (float4 + shfl assembly) + init CCL1
    k_pack<<<NN / 4 / TPB, TPB>>>(in);

    // --- remove_small_objects(fg, 2000, guarded) ---
    k_merge<false><<<gw, TPB>>>(F, L0);
    k_count<false, true><<<gw, TPB>>>(F, L0, S0);
    k_filter_init<<<gw, TPB>>>(F, 2000);         // + init hole-CCL (buf 1)

    // --- fill small holes: bg components < 301 px ---
    k_merge<true><<<gw, TPB>>>(F, L1);
    k_count<true, false><<<gw, TPB>>>(F, L1, S1);
    k_fill<<<gw, TPB>>>(F, 301);

    // --- erode disk(2), then opening disk(5) ---
    k_morph<2, true , false><<<gw, TPB>>>(F, G);
    k_morph<5, true , false><<<gw, TPB>>>(G, F);
    k_morph<5, false, true ><<<gw, TPB>>>(F, G); // + init CCL3 (buf 0)

    // --- remove_small_objects(fg, 2000, guarded) on G ---
    k_merge<false><<<gw, TPB>>>(G, L0);
    k_count<false, true><<<gw, TPB>>>(G, L0, S0);
    k_filter<<<gw, TPB>>>(G, 2000);

    // --- dilate disk(1) -> float out ---
    k_out<<<gp, TPB>>>(G, out);
}